// round 16
// baseline (speedup 1.0000x reference)
#include <cuda_runtime.h>
#include <cstdint>

#define NN 50000      // nodes
#define NE 1250000    // edges
#define DN 64         // node feat
#define DE 16         // edge feat
#define DH 64         // hidden

// ---------------------------------------------------------------------------
// Scratch (device globals; no allocation allowed)
// ---------------------------------------------------------------------------
__device__ float g_srcpart[NN * DH];   // node_features @ W_m1[0:64]
__device__ float g_xu[NN * DH];        // node_features @ W_u1[0:64]
__device__ float g_hsum[NN * DH];      // segment-sum of relu hidden
__device__ int   g_deg[NN];            // in-degree per node
__device__ float g_Wc[DH * DH];        // W_m2 @ W_u1[64:128]
__device__ float g_bc[DH];             // b_m2 @ W_u1[64:128]

// ---------------------------------------------------------------------------
// init: blocks [0,ZB) zero g_hsum/g_deg.
//       blocks ZB+k (k<64): Wc row k (coalesced over tid).  block ZB+64: bc.
// ---------------------------------------------------------------------------
#define ZB 3125   // NN*DH/4 / 256
__global__ void init_kernel(const float* __restrict__ w_m2,
                            const float* __restrict__ b_m2,
                            const float* __restrict__ w_u1) {
    const int tid = threadIdx.x;
    if (blockIdx.x < ZB) {
        int idx = blockIdx.x * 256 + tid;
        reinterpret_cast<float4*>(g_hsum)[idx] = make_float4(0.f, 0.f, 0.f, 0.f);
        if (idx < NN) g_deg[idx] = 0;
    } else if (blockIdx.x < ZB + 64) {
        int k = blockIdx.x - ZB;
        if (tid < DH) {
            float s = 0.f;
            #pragma unroll 8
            for (int m = 0; m < DH; m++)
                s += w_m2[k * DH + m] * w_u1[(DN + m) * DH + tid];
            g_Wc[k * DH + tid] = s;
        }
    } else {
        if (tid < DH) {
            float s = 0.f;
            #pragma unroll 8
            for (int m = 0; m < DH; m++)
                s += b_m2[m] * w_u1[(DN + m) * DH + tid];
            g_bc[tid] = s;
        }
    }
}

// ---------------------------------------------------------------------------
// pre: srcpart = X @ w_m1[0:64] only (128-row tiles, 8x4/thread).
// ---------------------------------------------------------------------------
#define PGB 391    // ceil(NN/128)
__global__ void pre_srcpart_kernel(const float* __restrict__ X,
                                   const float* __restrict__ w_m1) {
    __shared__ float As[128 * 66];
    const int row0 = blockIdx.x * 128;
    const int tid = threadIdx.x;

    for (int idx = tid; idx < 128 * 64; idx += 256) {
        int r = idx >> 6, k = idx & 63;
        int row = row0 + r;
        As[r * 66 + k] = (row < NN) ? X[(size_t)row * 64 + k] : 0.f;
    }
    __syncthreads();

    const int tc = tid & 15, tr = tid >> 4;
    const int j0 = tc * 4, r0 = tr * 8;
    float4 acc[8];
    #pragma unroll
    for (int i = 0; i < 8; i++) acc[i] = make_float4(0.f, 0.f, 0.f, 0.f);
    #pragma unroll 8
    for (int k = 0; k < 64; k++) {
        float4 w = *reinterpret_cast<const float4*>(&w_m1[k * 64 + j0]);
        #pragma unroll
        for (int i = 0; i < 8; i++) {
            float a = As[(r0 + i) * 66 + k];
            acc[i].x += a * w.x; acc[i].y += a * w.y;
            acc[i].z += a * w.z; acc[i].w += a * w.w;
        }
    }
    #pragma unroll
    for (int i = 0; i < 8; i++) {
        int row = row0 + r0 + i;
        if (row < NN)
            *reinterpret_cast<float4*>(&g_srcpart[(size_t)row * 64 + j0]) = acc[i];
    }
}

// ---------------------------------------------------------------------------
// edge_mix: 20925 blocks.  Side blocks (xu GEMM / deg histogram) are
// INTERLEAVED 1-in-15 through the edge grid so every wave keeps the LTS
// REDG stream saturated while side blocks consume idle FMA/issue slots.
// ---------------------------------------------------------------------------
#define EB    19532   // ceil(NE/64)
#define XUB   782     // ceil(NN/64)
#define DEGB  611     // ceil(NE/(256*8))
#define NSIDE (XUB + DEGB)   // 1393
#define TOTB  (EB + NSIDE)   // 20925
__global__ void __launch_bounds__(256, 4)
edge_mix_kernel(const float* __restrict__ ef,
                const int* __restrict__ eidx,
                const float* __restrict__ w_m1,
                const float* __restrict__ b_m1,
                const float* __restrict__ X,
                const float* __restrict__ w_u1) {
    __shared__ float Sh[64 * 66];   // union: edge uses a prefix, xu uses all
    const int tid = threadIdx.x;
    const int b = blockIdx.x;
    const int sq = b / 15;
    const bool isSide = ((b % 15) == 7) && (sq < NSIDE);

    if (isSide) {
        if (sq >= XUB) {
            // ---- deg histogram: 2048 edges ----
            int base = (sq - XUB) * 2048 + tid;
            #pragma unroll
            for (int i = 0; i < 8; i++) {
                int e = base + i * 256;
                if (e < NE) atomicAdd(&g_deg[eidx[NE + e]], 1);
            }
            return;
        }
        // ---- xu = X @ w_u1[0:64], 64-row tile, 4 rows x 4 cols/thread ----
        const int row0 = sq * 64;
        for (int idx = tid; idx < 64 * 64; idx += 256) {
            int r = idx >> 6, k = idx & 63;
            int row = row0 + r;
            Sh[r * 66 + k] = (row < NN) ? X[(size_t)row * 64 + k] : 0.f;
        }
        __syncthreads();

        const int tc = tid & 15, tr = tid >> 4;
        const int j0 = tc * 4, r0 = tr * 4;
        float4 acc[4];
        #pragma unroll
        for (int i = 0; i < 4; i++) acc[i] = make_float4(0.f, 0.f, 0.f, 0.f);
        #pragma unroll 8
        for (int k = 0; k < 64; k++) {
            float4 w = *reinterpret_cast<const float4*>(&w_u1[k * 64 + j0]);
            #pragma unroll
            for (int i = 0; i < 4; i++) {
                float a = Sh[(r0 + i) * 66 + k];
                acc[i].x += a * w.x; acc[i].y += a * w.y;
                acc[i].z += a * w.z; acc[i].w += a * w.w;
            }
        }
        #pragma unroll
        for (int i = 0; i < 4; i++) {
            int row = row0 + r0 + i;
            if (row < NN)
                *reinterpret_cast<float4*>(&g_xu[(size_t)row * 64 + j0]) = acc[i];
        }
        return;
    }

    // ---- edge message + scatter (exact R7 config) ----
    int nside_before = (b + 7) / 15;
    if (nside_before > NSIDE) nside_before = NSIDE;
    const int eb = b - nside_before;

    float* Es = Sh;                         // 64*17 floats
    int* s_sh = reinterpret_cast<int*>(Sh + 64 * 17);
    int* d_sh = s_sh + 64;
    const int e0 = eb * 64;

    if (tid < 64) {
        int e = e0 + tid;
        int s = 0, d = 0;
        if (e < NE) {
            s = eidx[e];
            d = eidx[NE + e];
        }
        s_sh[tid] = s;
        d_sh[tid] = d;
    }
    {
        int r = tid >> 2, q = tid & 3;   // 64 edges x 4 float4 = 256 loads
        int e = e0 + r;
        float4 v = make_float4(0.f, 0.f, 0.f, 0.f);
        if (e < NE)
            v = reinterpret_cast<const float4*>(ef)[(size_t)e * 4 + q];
        Es[r * 17 + q * 4 + 0] = v.x;
        Es[r * 17 + q * 4 + 1] = v.y;
        Es[r * 17 + q * 4 + 2] = v.z;
        Es[r * 17 + q * 4 + 3] = v.w;
    }
    __syncthreads();

    const int tc = tid & 15, tr = tid >> 4;
    const int j0 = tc * 4, r0 = tr * 4;

    // Prefetch the 4 srcpart gathers early (independent L2 hits, MLP=4).
    float4 sp[4];
    #pragma unroll
    for (int i = 0; i < 4; i++) {
        int e = e0 + r0 + i;
        const float* p = &g_srcpart[(size_t)s_sh[r0 + i] * 64 + j0];
        sp[i] = (e < NE) ? *reinterpret_cast<const float4*>(p)
                         : make_float4(0.f, 0.f, 0.f, 0.f);
    }

    float4 acc[4];
    #pragma unroll
    for (int i = 0; i < 4; i++) acc[i] = make_float4(0.f, 0.f, 0.f, 0.f);

    #pragma unroll
    for (int k = 0; k < 16; k++) {
        float4 w = *reinterpret_cast<const float4*>(&w_m1[(DN + k) * 64 + j0]);
        #pragma unroll
        for (int i = 0; i < 4; i++) {
            float a = Es[(r0 + i) * 17 + k];
            acc[i].x += a * w.x; acc[i].y += a * w.y;
            acc[i].z += a * w.z; acc[i].w += a * w.w;
        }
    }

    float4 bb = *reinterpret_cast<const float4*>(&b_m1[j0]);

    #pragma unroll
    for (int i = 0; i < 4; i++) {
        int e = e0 + r0 + i;
        if (e < NE) {
            float hx = fmaxf(acc[i].x + sp[i].x + bb.x, 0.f);
            float hy = fmaxf(acc[i].y + sp[i].y + bb.y, 0.f);
            float hz = fmaxf(acc[i].z + sp[i].z + bb.z, 0.f);
            float hw = fmaxf(acc[i].w + sp[i].w + bb.w, 0.f);
            float* p = &g_hsum[(size_t)d_sh[r0 + i] * 64 + j0];
            asm volatile("red.global.add.v4.f32 [%0], {%1, %2, %3, %4};"
                         :: "l"(p), "f"(hx), "f"(hy), "f"(hz), "f"(hw)
                         : "memory");
        }
    }
}

// ---------------------------------------------------------------------------
// Fused node update (R7 config): 128-row tiles, 8 rows x 4 cols/thread.
//   T = relu(Hsum@Wc + xu + deg*bc + b_u1);  out = T @ w_u2 + b_u2
// ---------------------------------------------------------------------------
__global__ void fused_node_kernel(const float* __restrict__ w_u2,
                                  const float* __restrict__ b_u1,
                                  const float* __restrict__ b_u2,
                                  float* __restrict__ out) {
    __shared__ float As[128 * 66];
    const int row0 = blockIdx.x * 128;
    const int tid = threadIdx.x;
    const int tc = tid & 15, tr = tid >> 4;
    const int j0 = tc * 4, r0 = tr * 8;

    for (int idx = tid; idx < 128 * 64; idx += 256) {
        int r = idx >> 6, k = idx & 63;
        int row = row0 + r;
        As[r * 66 + k] = (row < NN) ? g_hsum[(size_t)row * 64 + k] : 0.f;
    }
    __syncthreads();

    float4 acc[8];
    #pragma unroll
    for (int i = 0; i < 8; i++) acc[i] = make_float4(0.f, 0.f, 0.f, 0.f);
    #pragma unroll 8
    for (int k = 0; k < 64; k++) {
        float4 w = *reinterpret_cast<const float4*>(&g_Wc[k * 64 + j0]);
        #pragma unroll
        for (int i = 0; i < 8; i++) {
            float a = As[(r0 + i) * 66 + k];
            acc[i].x += a * w.x; acc[i].y += a * w.y;
            acc[i].z += a * w.z; acc[i].w += a * w.w;
        }
    }
    __syncthreads();

    {
        float4 bc = *reinterpret_cast<const float4*>(&g_bc[j0]);
        float4 bu = *reinterpret_cast<const float4*>(&b_u1[j0]);
        #pragma unroll
        for (int i = 0; i < 8; i++) {
            int r = r0 + i;
            int row = row0 + r;
            if (row < NN) {
                float4 xu = *reinterpret_cast<const float4*>(
                    &g_xu[(size_t)row * 64 + j0]);
                float dg = (float)g_deg[row];
                As[r * 66 + j0 + 0] = fmaxf(acc[i].x + xu.x + dg * bc.x + bu.x, 0.f);
                As[r * 66 + j0 + 1] = fmaxf(acc[i].y + xu.y + dg * bc.y + bu.y, 0.f);
                As[r * 66 + j0 + 2] = fmaxf(acc[i].z + xu.z + dg * bc.z + bu.z, 0.f);
                As[r * 66 + j0 + 3] = fmaxf(acc[i].w + xu.w + dg * bc.w + bu.w, 0.f);
            } else {
                As[r * 66 + j0 + 0] = 0.f;
                As[r * 66 + j0 + 1] = 0.f;
                As[r * 66 + j0 + 2] = 0.f;
                As[r * 66 + j0 + 3] = 0.f;
            }
        }
    }
    __syncthreads();

    #pragma unroll
    for (int i = 0; i < 8; i++) acc[i] = make_float4(0.f, 0.f, 0.f, 0.f);
    #pragma unroll 8
    for (int k = 0; k < 64; k++) {
        float4 w = *reinterpret_cast<const float4*>(&w_u2[k * 64 + j0]);
        #pragma unroll
        for (int i = 0; i < 8; i++) {
            float a = As[(r0 + i) * 66 + k];
            acc[i].x += a * w.x; acc[i].y += a * w.y;
            acc[i].z += a * w.z; acc[i].w += a * w.w;
        }
    }

    float4 b2 = *reinterpret_cast<const float4*>(&b_u2[j0]);
    #pragma unroll
    for (int i = 0; i < 8; i++) {
        int row = row0 + r0 + i;
        if (row < NN) {
            float4 v;
            v.x = acc[i].x + b2.x; v.y = acc[i].y + b2.y;
            v.z = acc[i].z + b2.z; v.w = acc[i].w + b2.w;
            *reinterpret_cast<float4*>(&out[(size_t)row * 64 + j0]) = v;
        }
    }
}

// ---------------------------------------------------------------------------
// Launch: fork/join overlap of init (side stream) with pre (main stream).
// init writes {hsum, deg, Wc, bc}; pre writes srcpart — fully independent.
// Both joined before edge_mix.  Capture-legal multi-stream pattern.
// ---------------------------------------------------------------------------
extern "C" void kernel_launch(void* const* d_in, const int* in_sizes, int n_in,
                              void* d_out, int out_size) {
    const float* node_f = (const float*)d_in[0];
    const float* edge_f = (const float*)d_in[1];
    const int*   eidx   = (const int*)d_in[2];
    const float* w_m1   = (const float*)d_in[3];
    const float* b_m1   = (const float*)d_in[4];
    const float* w_m2   = (const float*)d_in[5];
    const float* b_m2   = (const float*)d_in[6];
    const float* w_u1   = (const float*)d_in[7];
    const float* b_u1   = (const float*)d_in[8];
    const float* w_u2   = (const float*)d_in[9];
    const float* b_u2   = (const float*)d_in[10];
    float* out = (float*)d_out;

    cudaStream_t s1;
    cudaStreamCreate(&s1);
    cudaEvent_t evFork, evJoin;
    cudaEventCreateWithFlags(&evFork, cudaEventDisableTiming);
    cudaEventCreateWithFlags(&evJoin, cudaEventDisableTiming);

    // fork: init on s1, pre on the main stream — independent work
    cudaEventRecord(evFork, 0);
    cudaStreamWaitEvent(s1, evFork, 0);
    init_kernel<<<ZB + 65, 256, 0, s1>>>(w_m2, b_m2, w_u1);
    cudaEventRecord(evJoin, s1);

    pre_srcpart_kernel<<<PGB, 256>>>(node_f, w_m1);

    // join: edge needs srcpart (main) + zeroed hsum/deg (s1)
    cudaStreamWaitEvent(0, evJoin, 0);
    edge_mix_kernel<<<TOTB, 256>>>(edge_f, eidx, w_m1, b_m1, node_f, w_u1);
    fused_node_kernel<<<PGB, 256>>>(w_u2, b_u1, b_u2, out);
}

// round 17
// speedup vs baseline: 1.5234x; 1.5234x over previous
#include <cuda_runtime.h>
#include <cstdint>

#define NN 50000      // nodes
#define NE 1250000    // edges
#define DN 64         // node feat
#define DE 16         // edge feat
#define DH 64         // hidden

// ---------------------------------------------------------------------------
// Scratch (device globals; no allocation allowed)
// ---------------------------------------------------------------------------
__device__ float g_srcpart[NN * DH];   // node_features @ W_m1[0:64]
__device__ float g_xu[NN * DH];        // node_features @ W_u1[0:64]
__device__ float g_hsum[NN * DH];      // segment-sum of relu hidden
__device__ int   g_deg[NN];            // in-degree per node
__device__ float g_Wc[DH * DH];        // W_m2 @ W_u1[64:128]
__device__ float g_bc[DH];             // b_m2 @ W_u1[64:128]

// ---------------------------------------------------------------------------
// init: blocks [0,ZB) zero g_hsum/g_deg.
//       blocks ZB+k (k<64): Wc row k (coalesced over tid).  block ZB+64: bc.
// ---------------------------------------------------------------------------
#define ZB 3125   // NN*DH/4 / 256
__global__ void init_kernel(const float* __restrict__ w_m2,
                            const float* __restrict__ b_m2,
                            const float* __restrict__ w_u1) {
    const int tid = threadIdx.x;
    if (blockIdx.x < ZB) {
        int idx = blockIdx.x * 256 + tid;
        reinterpret_cast<float4*>(g_hsum)[idx] = make_float4(0.f, 0.f, 0.f, 0.f);
        if (idx < NN) g_deg[idx] = 0;
    } else if (blockIdx.x < ZB + 64) {
        int k = blockIdx.x - ZB;
        if (tid < DH) {
            float s = 0.f;
            #pragma unroll 8
            for (int m = 0; m < DH; m++)
                s += w_m2[k * DH + m] * w_u1[(DN + m) * DH + tid];
            g_Wc[k * DH + tid] = s;
        }
    } else {
        if (tid < DH) {
            float s = 0.f;
            #pragma unroll 8
            for (int m = 0; m < DH; m++)
                s += b_m2[m] * w_u1[(DN + m) * DH + tid];
            g_bc[tid] = s;
        }
    }
}

// ---------------------------------------------------------------------------
// pre: srcpart = X @ w_m1[0:64] only (128-row tiles, 8x4/thread).
// ---------------------------------------------------------------------------
#define PGB 391    // ceil(NN/128)
__global__ void pre_srcpart_kernel(const float* __restrict__ X,
                                   const float* __restrict__ w_m1) {
    __shared__ float As[128 * 66];
    const int row0 = blockIdx.x * 128;
    const int tid = threadIdx.x;

    for (int idx = tid; idx < 128 * 64; idx += 256) {
        int r = idx >> 6, k = idx & 63;
        int row = row0 + r;
        As[r * 66 + k] = (row < NN) ? X[(size_t)row * 64 + k] : 0.f;
    }
    __syncthreads();

    const int tc = tid & 15, tr = tid >> 4;
    const int j0 = tc * 4, r0 = tr * 8;
    float4 acc[8];
    #pragma unroll
    for (int i = 0; i < 8; i++) acc[i] = make_float4(0.f, 0.f, 0.f, 0.f);
    #pragma unroll 8
    for (int k = 0; k < 64; k++) {
        float4 w = *reinterpret_cast<const float4*>(&w_m1[k * 64 + j0]);
        #pragma unroll
        for (int i = 0; i < 8; i++) {
            float a = As[(r0 + i) * 66 + k];
            acc[i].x += a * w.x; acc[i].y += a * w.y;
            acc[i].z += a * w.z; acc[i].w += a * w.w;
        }
    }
    #pragma unroll
    for (int i = 0; i < 8; i++) {
        int row = row0 + r0 + i;
        if (row < NN)
            *reinterpret_cast<float4*>(&g_srcpart[(size_t)row * 64 + j0]) = acc[i];
    }
}

// ---------------------------------------------------------------------------
// edge_mix: 20925 blocks.  Side blocks (xu GEMM / deg histogram) are
// INTERLEAVED 1-in-15 through the edge grid so every wave keeps the LTS
// REDG stream saturated while side blocks consume idle FMA/issue slots.
// ---------------------------------------------------------------------------
#define EB    19532   // ceil(NE/64)
#define XUB   782     // ceil(NN/64)
#define DEGB  611     // ceil(NE/(256*8))
#define NSIDE (XUB + DEGB)   // 1393
#define TOTB  (EB + NSIDE)   // 20925
__global__ void __launch_bounds__(256, 4)
edge_mix_kernel(const float* __restrict__ ef,
                const int* __restrict__ eidx,
                const float* __restrict__ w_m1,
                const float* __restrict__ b_m1,
                const float* __restrict__ X,
                const float* __restrict__ w_u1) {
    __shared__ float Sh[64 * 66];   // union: edge uses a prefix, xu uses all
    const int tid = threadIdx.x;
    const int b = blockIdx.x;
    const int sq = b / 15;
    const bool isSide = ((b % 15) == 7) && (sq < NSIDE);

    if (isSide) {
        if (sq >= XUB) {
            // ---- deg histogram: 2048 edges ----
            int base = (sq - XUB) * 2048 + tid;
            #pragma unroll
            for (int i = 0; i < 8; i++) {
                int e = base + i * 256;
                if (e < NE) atomicAdd(&g_deg[eidx[NE + e]], 1);
            }
            return;
        }
        // ---- xu = X @ w_u1[0:64], 64-row tile, 4 rows x 4 cols/thread ----
        const int row0 = sq * 64;
        for (int idx = tid; idx < 64 * 64; idx += 256) {
            int r = idx >> 6, k = idx & 63;
            int row = row0 + r;
            Sh[r * 66 + k] = (row < NN) ? X[(size_t)row * 64 + k] : 0.f;
        }
        __syncthreads();

        const int tc = tid & 15, tr = tid >> 4;
        const int j0 = tc * 4, r0 = tr * 4;
        float4 acc[4];
        #pragma unroll
        for (int i = 0; i < 4; i++) acc[i] = make_float4(0.f, 0.f, 0.f, 0.f);
        #pragma unroll 8
        for (int k = 0; k < 64; k++) {
            float4 w = *reinterpret_cast<const float4*>(&w_u1[k * 64 + j0]);
            #pragma unroll
            for (int i = 0; i < 4; i++) {
                float a = Sh[(r0 + i) * 66 + k];
                acc[i].x += a * w.x; acc[i].y += a * w.y;
                acc[i].z += a * w.z; acc[i].w += a * w.w;
            }
        }
        #pragma unroll
        for (int i = 0; i < 4; i++) {
            int row = row0 + r0 + i;
            if (row < NN)
                *reinterpret_cast<float4*>(&g_xu[(size_t)row * 64 + j0]) = acc[i];
        }
        return;
    }

    // ---- edge message + scatter (exact R7 config) ----
    int nside_before = (b + 7) / 15;
    if (nside_before > NSIDE) nside_before = NSIDE;
    const int eb = b - nside_before;

    float* Es = Sh;                         // 64*17 floats
    int* s_sh = reinterpret_cast<int*>(Sh + 64 * 17);
    int* d_sh = s_sh + 64;
    const int e0 = eb * 64;

    if (tid < 64) {
        int e = e0 + tid;
        int s = 0, d = 0;
        if (e < NE) {
            s = eidx[e];
            d = eidx[NE + e];
        }
        s_sh[tid] = s;
        d_sh[tid] = d;
    }
    {
        int r = tid >> 2, q = tid & 3;   // 64 edges x 4 float4 = 256 loads
        int e = e0 + r;
        float4 v = make_float4(0.f, 0.f, 0.f, 0.f);
        if (e < NE)
            v = reinterpret_cast<const float4*>(ef)[(size_t)e * 4 + q];
        Es[r * 17 + q * 4 + 0] = v.x;
        Es[r * 17 + q * 4 + 1] = v.y;
        Es[r * 17 + q * 4 + 2] = v.z;
        Es[r * 17 + q * 4 + 3] = v.w;
    }
    __syncthreads();

    const int tc = tid & 15, tr = tid >> 4;
    const int j0 = tc * 4, r0 = tr * 4;

    // Prefetch the 4 srcpart gathers early (independent L2 hits, MLP=4).
    float4 sp[4];
    #pragma unroll
    for (int i = 0; i < 4; i++) {
        int e = e0 + r0 + i;
        const float* p = &g_srcpart[(size_t)s_sh[r0 + i] * 64 + j0];
        sp[i] = (e < NE) ? *reinterpret_cast<const float4*>(p)
                         : make_float4(0.f, 0.f, 0.f, 0.f);
    }

    float4 acc[4];
    #pragma unroll
    for (int i = 0; i < 4; i++) acc[i] = make_float4(0.f, 0.f, 0.f, 0.f);

    #pragma unroll
    for (int k = 0; k < 16; k++) {
        float4 w = *reinterpret_cast<const float4*>(&w_m1[(DN + k) * 64 + j0]);
        #pragma unroll
        for (int i = 0; i < 4; i++) {
            float a = Es[(r0 + i) * 17 + k];
            acc[i].x += a * w.x; acc[i].y += a * w.y;
            acc[i].z += a * w.z; acc[i].w += a * w.w;
        }
    }

    float4 bb = *reinterpret_cast<const float4*>(&b_m1[j0]);

    #pragma unroll
    for (int i = 0; i < 4; i++) {
        int e = e0 + r0 + i;
        if (e < NE) {
            float hx = fmaxf(acc[i].x + sp[i].x + bb.x, 0.f);
            float hy = fmaxf(acc[i].y + sp[i].y + bb.y, 0.f);
            float hz = fmaxf(acc[i].z + sp[i].z + bb.z, 0.f);
            float hw = fmaxf(acc[i].w + sp[i].w + bb.w, 0.f);
            float* p = &g_hsum[(size_t)d_sh[r0 + i] * 64 + j0];
            asm volatile("red.global.add.v4.f32 [%0], {%1, %2, %3, %4};"
                         :: "l"(p), "f"(hx), "f"(hy), "f"(hz), "f"(hw)
                         : "memory");
        }
    }
}

// ---------------------------------------------------------------------------
// Fused node update (R7 config): 128-row tiles, 8 rows x 4 cols/thread.
//   T = relu(Hsum@Wc + xu + deg*bc + b_u1);  out = T @ w_u2 + b_u2
// ---------------------------------------------------------------------------
__global__ void fused_node_kernel(const float* __restrict__ w_u2,
                                  const float* __restrict__ b_u1,
                                  const float* __restrict__ b_u2,
                                  float* __restrict__ out) {
    __shared__ float As[128 * 66];
    const int row0 = blockIdx.x * 128;
    const int tid = threadIdx.x;
    const int tc = tid & 15, tr = tid >> 4;
    const int j0 = tc * 4, r0 = tr * 8;

    for (int idx = tid; idx < 128 * 64; idx += 256) {
        int r = idx >> 6, k = idx & 63;
        int row = row0 + r;
        As[r * 66 + k] = (row < NN) ? g_hsum[(size_t)row * 64 + k] : 0.f;
    }
    __syncthreads();

    float4 acc[8];
    #pragma unroll
    for (int i = 0; i < 8; i++) acc[i] = make_float4(0.f, 0.f, 0.f, 0.f);
    #pragma unroll 8
    for (int k = 0; k < 64; k++) {
        float4 w = *reinterpret_cast<const float4*>(&g_Wc[k * 64 + j0]);
        #pragma unroll
        for (int i = 0; i < 8; i++) {
            float a = As[(r0 + i) * 66 + k];
            acc[i].x += a * w.x; acc[i].y += a * w.y;
            acc[i].z += a * w.z; acc[i].w += a * w.w;
        }
    }
    __syncthreads();

    {
        float4 bc = *reinterpret_cast<const float4*>(&g_bc[j0]);
        float4 bu = *reinterpret_cast<const float4*>(&b_u1[j0]);
        #pragma unroll
        for (int i = 0; i < 8; i++) {
            int r = r0 + i;
            int row = row0 + r;
            if (row < NN) {
                float4 xu = *reinterpret_cast<const float4*>(
                    &g_xu[(size_t)row * 64 + j0]);
                float dg = (float)g_deg[row];
                As[r * 66 + j0 + 0] = fmaxf(acc[i].x + xu.x + dg * bc.x + bu.x, 0.f);
                As[r * 66 + j0 + 1] = fmaxf(acc[i].y + xu.y + dg * bc.y + bu.y, 0.f);
                As[r * 66 + j0 + 2] = fmaxf(acc[i].z + xu.z + dg * bc.z + bu.z, 0.f);
                As[r * 66 + j0 + 3] = fmaxf(acc[i].w + xu.w + dg * bc.w + bu.w, 0.f);
            } else {
                As[r * 66 + j0 + 0] = 0.f;
                As[r * 66 + j0 + 1] = 0.f;
                As[r * 66 + j0 + 2] = 0.f;
                As[r * 66 + j0 + 3] = 0.f;
            }
        }
    }
    __syncthreads();

    #pragma unroll
    for (int i = 0; i < 8; i++) acc[i] = make_float4(0.f, 0.f, 0.f, 0.f);
    #pragma unroll 8
    for (int k = 0; k < 64; k++) {
        float4 w = *reinterpret_cast<const float4*>(&w_u2[k * 64 + j0]);
        #pragma unroll
        for (int i = 0; i < 8; i++) {
            float a = As[(r0 + i) * 66 + k];
            acc[i].x += a * w.x; acc[i].y += a * w.y;
            acc[i].z += a * w.z; acc[i].w += a * w.w;
        }
    }

    float4 b2 = *reinterpret_cast<const float4*>(&b_u2[j0]);
    #pragma unroll
    for (int i = 0; i < 8; i++) {
        int row = row0 + r0 + i;
        if (row < NN) {
            float4 v;
            v.x = acc[i].x + b2.x; v.y = acc[i].y + b2.y;
            v.z = acc[i].z + b2.z; v.w = acc[i].w + b2.w;
            *reinterpret_cast<float4*>(&out[(size_t)row * 64 + j0]) = v;
        }
    }
}

// ---------------------------------------------------------------------------
// Launch (single stream, linear chain — measured optimal)
// ---------------------------------------------------------------------------
extern "C" void kernel_launch(void* const* d_in, const int* in_sizes, int n_in,
                              void* d_out, int out_size) {
    const float* node_f = (const float*)d_in[0];
    const float* edge_f = (const float*)d_in[1];
    const int*   eidx   = (const int*)d_in[2];
    const float* w_m1   = (const float*)d_in[3];
    const float* b_m1   = (const float*)d_in[4];
    const float* w_m2   = (const float*)d_in[5];
    const float* b_m2   = (const float*)d_in[6];
    const float* w_u1   = (const float*)d_in[7];
    const float* b_u1   = (const float*)d_in[8];
    const float* w_u2   = (const float*)d_in[9];
    const float* b_u2   = (const float*)d_in[10];
    float* out = (float*)d_out;

    init_kernel<<<ZB + 65, 256>>>(w_m2, b_m2, w_u1);
    pre_srcpart_kernel<<<PGB, 256>>>(node_f, w_m1);
    edge_mix_kernel<<<TOTB, 256>>>(edge_f, eidx, w_m1, b_m1, node_f, w_u1);
    fused_node_kernel<<<PGB, 256>>>(w_u2, b_u1, b_u2, out);
}